// round 16
// baseline (speedup 1.0000x reference)
#include <cuda_runtime.h>
#include <cuda_bf16.h>

#define N_NODES 100000
#define N_EDGES 1600000
#define IN_FT   128
#define OUT_FT  32

#define TILE_NODES 256
#define KTILE      32          // k per phase (8 float4)
#define ROW_F4     9           // 8 float4 + 1 pad -> conflict-free LDS.128

#define CAP        64          // slots per row; Poisson(16) => P(overflow) ~ 1e-18

#define GEMM_BLOCKS ((N_NODES + TILE_NODES - 1) / TILE_NODES)   // 391
#define BIN_BLOCKS  ((N_EDGES + 255) / 256)                     // 6250

// Device-global scratch (no allocs allowed). Zero-initialized at module load;
// the gather kernel restores g_cnt/g_ovf_cnt to 0 at the end of every call,
// so the invariant "counters are 0 at kernel_launch entry" holds across the
// correctness run and all graph replays.
__device__ float  g_support[(size_t)N_NODES * OUT_FT];        // 12.8 MB
__device__ float2 g_binned[(size_t)N_NODES * CAP];            // 51.2 MB
__device__ int    g_cnt[N_NODES];
__device__ int    g_ovf_cnt;
__device__ int    g_ovf_row[N_EDGES];                         // correctness fallback
__device__ int    g_ovf_col[N_EDGES];
__device__ float  g_ovf_val[N_EDGES];

// ---------------------------------------------------------------------------
// Kernel 1 (fused): blocks [0, GEMM_BLOCKS) compute support = seq @ W
// (register-tiled, 256 nodes/block); blocks [GEMM_BLOCKS, ...) bin edges by
// destination row. The two paths touch disjoint resources (FFMA+smem vs
// L2 atomics), so the bin work hides under the GEMM.
// ---------------------------------------------------------------------------
__global__ __launch_bounds__(256, 3) void gcn_gemm_bin_kernel(
        const float* __restrict__ seq,
        const float* __restrict__ W,
        const int*   __restrict__ erow,
        const int*   __restrict__ ecol,
        const float* __restrict__ eval) {
    const int tid = threadIdx.x;

    if (blockIdx.x >= GEMM_BLOCKS) {
        // ---- bin path ----
        int e = (blockIdx.x - GEMM_BLOCKS) * 256 + tid;
        if (e >= N_EDGES) return;

        int r = erow[e];
        int c = ecol[e];
        float v = eval[e];

        int pos = atomicAdd(&g_cnt[r], 1);
        if (pos < CAP) {
            g_binned[(size_t)r * CAP + pos] = make_float2(__int_as_float(c), v);
        } else {
            int o = atomicAdd(&g_ovf_cnt, 1);
            g_ovf_row[o] = r;
            g_ovf_col[o] = c;
            g_ovf_val[o] = v;
        }
        return;
    }

    // ---- GEMM path ----
    __shared__ float4 ssm[TILE_NODES * ROW_F4];   // 36 KB
    __shared__ float  Wsm[KTILE * OUT_FT];        // 4 KB

    const int node_base = blockIdx.x * TILE_NODES;
    const int n_slot = tid >> 2;          // 0..63
    const int j0     = (tid & 3) * 8;     // 0,8,16,24

    float acc[4][8];
    #pragma unroll
    for (int i = 0; i < 4; i++)
        #pragma unroll
        for (int j = 0; j < 8; j++) acc[i][j] = 0.f;

    const float4* seq4 = reinterpret_cast<const float4*>(seq);

    for (int kp = 0; kp < IN_FT / KTILE; kp++) {
        __syncthreads();

        reinterpret_cast<float4*>(Wsm)[tid] =
            reinterpret_cast<const float4*>(W)[kp * (KTILE * OUT_FT / 4) + tid];

        #pragma unroll
        for (int t = 0; t < 8; t++) {
            int idx = tid + t * 256;
            int row = idx >> 3;
            int k4  = idx & 7;
            int node = node_base + row;
            float4 v = make_float4(0.f, 0.f, 0.f, 0.f);
            if (node < N_NODES)
                v = seq4[(size_t)node * (IN_FT / 4) + kp * 8 + k4];
            ssm[row * ROW_F4 + k4] = v;
        }
        __syncthreads();

        #pragma unroll 2
        for (int k4 = 0; k4 < KTILE / 4; k4++) {
            float4 a0 = ssm[(n_slot      ) * ROW_F4 + k4];
            float4 a1 = ssm[(n_slot +  64) * ROW_F4 + k4];
            float4 a2 = ssm[(n_slot + 128) * ROW_F4 + k4];
            float4 a3 = ssm[(n_slot + 192) * ROW_F4 + k4];
            float a[4][4] = {{a0.x, a0.y, a0.z, a0.w},
                             {a1.x, a1.y, a1.z, a1.w},
                             {a2.x, a2.y, a2.z, a2.w},
                             {a3.x, a3.y, a3.z, a3.w}};
            #pragma unroll
            for (int kk = 0; kk < 4; kk++) {
                int k = k4 * 4 + kk;
                float4 w0 = *reinterpret_cast<const float4*>(&Wsm[k * OUT_FT + j0]);
                float4 w1 = *reinterpret_cast<const float4*>(&Wsm[k * OUT_FT + j0 + 4]);
                #pragma unroll
                for (int i = 0; i < 4; i++) {
                    acc[i][0] = fmaf(a[i][kk], w0.x, acc[i][0]);
                    acc[i][1] = fmaf(a[i][kk], w0.y, acc[i][1]);
                    acc[i][2] = fmaf(a[i][kk], w0.z, acc[i][2]);
                    acc[i][3] = fmaf(a[i][kk], w0.w, acc[i][3]);
                    acc[i][4] = fmaf(a[i][kk], w1.x, acc[i][4]);
                    acc[i][5] = fmaf(a[i][kk], w1.y, acc[i][5]);
                    acc[i][6] = fmaf(a[i][kk], w1.z, acc[i][6]);
                    acc[i][7] = fmaf(a[i][kk], w1.w, acc[i][7]);
                }
            }
        }
    }

    #pragma unroll
    for (int i = 0; i < 4; i++) {
        int node = node_base + n_slot + 64 * i;
        if (node < N_NODES) {
            float4* dst = reinterpret_cast<float4*>(&g_support[(size_t)node * OUT_FT + j0]);
            dst[0] = make_float4(acc[i][0], acc[i][1], acc[i][2], acc[i][3]);
            dst[1] = make_float4(acc[i][4], acc[i][5], acc[i][6], acc[i][7]);
        }
    }
}

// ---------------------------------------------------------------------------
// Kernel 2: gather + fused ReLU + counter cleanup. One warp per row,
// lane = output feature. Slots are staged into smem ZERO-PADDED to the next
// multiple of 8 (lanes >= n store {col=0,val=0}); the edge loop then runs
// n_pad iterations of the unconditional 8-wide body with NO remainder loop,
// eliminating the serial per-edge LDS->LDG->FFMA latency tail. Padding
// entries read support[0] (valid) and add fmaf(0,.) = exact +0.
// Each warp resets g_cnt[row]=0 after use (replaces the zero kernel).
// ---------------------------------------------------------------------------
__global__ __launch_bounds__(256) void gcn_gather_kernel(float* __restrict__ out) {
    __shared__ float2 ssl[8][CAP];    // 8 warps/block x 64 slots = 4 KB

    const int wib  = threadIdx.x >> 5;
    const int lane = threadIdx.x & 31;
    const int row  = blockIdx.x * 8 + wib;
    if (row >= N_NODES) return;

    // Independent loads issued back-to-back: slot half A, cnt, ovf counter.
    const float2* slots = &g_binned[(size_t)row * CAP];
    float2 sA = slots[lane];
    int deg = g_cnt[row];
    int nov = g_ovf_cnt;

    int n = deg < CAP ? deg : CAP;
    int n_pad = (n + 7) & ~7;

    const float2 z = make_float2(0.f, 0.f);   // col bits 0 -> support row 0
    ssl[wib][lane] = (lane < n) ? sA : z;
    if (n > 32) {                      // warp-uniform; ~1e-4 of rows
        float2 sB = slots[lane + 32];
        ssl[wib][lane + 32] = (lane + 32 < n) ? sB : z;
    }
    __syncwarp();

    float acc = 0.f;
    for (int e = 0; e < n_pad; e += 8) {
        float2 s0 = ssl[wib][e + 0];
        float2 s1 = ssl[wib][e + 1];
        float2 s2 = ssl[wib][e + 2];
        float2 s3 = ssl[wib][e + 3];
        float2 s4 = ssl[wib][e + 4];
        float2 s5 = ssl[wib][e + 5];
        float2 s6 = ssl[wib][e + 6];
        float2 s7 = ssl[wib][e + 7];
        float f0 = g_support[(size_t)__float_as_int(s0.x) * OUT_FT + lane];
        float f1 = g_support[(size_t)__float_as_int(s1.x) * OUT_FT + lane];
        float f2 = g_support[(size_t)__float_as_int(s2.x) * OUT_FT + lane];
        float f3 = g_support[(size_t)__float_as_int(s3.x) * OUT_FT + lane];
        float f4 = g_support[(size_t)__float_as_int(s4.x) * OUT_FT + lane];
        float f5 = g_support[(size_t)__float_as_int(s5.x) * OUT_FT + lane];
        float f6 = g_support[(size_t)__float_as_int(s6.x) * OUT_FT + lane];
        float f7 = g_support[(size_t)__float_as_int(s7.x) * OUT_FT + lane];
        acc = fmaf(s0.y, f0, acc);
        acc = fmaf(s1.y, f1, acc);
        acc = fmaf(s2.y, f2, acc);
        acc = fmaf(s3.y, f3, acc);
        acc = fmaf(s4.y, f4, acc);
        acc = fmaf(s5.y, f5, acc);
        acc = fmaf(s6.y, f6, acc);
        acc = fmaf(s7.y, f7, acc);
    }

    // Correctness fallback: apply any overflow edges targeting this row.
    if (nov > 0) {
        for (int i = 0; i < nov; i++) {
            if (g_ovf_row[i] == row)
                acc = fmaf(g_ovf_val[i],
                           g_support[(size_t)g_ovf_col[i] * OUT_FT + lane], acc);
        }
    }

    out[(size_t)row * OUT_FT + lane] = fmaxf(acc, 0.f);

    // Cleanup for the next call/replay (deg was already consumed above).
    if (lane == 0) g_cnt[row] = 0;
    if (row == 0 && lane == 0) g_ovf_cnt = 0;
}

extern "C" void kernel_launch(void* const* d_in, const int* in_sizes, int n_in,
                              void* d_out, int out_size) {
    const float* seq  = (const float*)d_in[0];
    const float* W    = (const float*)d_in[1];
    const int*   erow = (const int*)d_in[2];
    const int*   ecol = (const int*)d_in[3];
    const float* eval = (const float*)d_in[4];
    float* out = (float*)d_out;

    // Fused GEMM (blocks [0,391)) + edge binning (blocks [391, 6641)).
    // Counters are 0 on entry (zero-init at load; reset by gather each call).
    gcn_gemm_bin_kernel<<<GEMM_BLOCKS + BIN_BLOCKS, 256>>>(seq, W, erow, ecol, eval);

    // Gather + ReLU + counter cleanup (writes every output element once).
    gcn_gather_kernel<<<(N_NODES + 7) / 8, 256>>>(out);
}

// round 17
// speedup vs baseline: 1.1192x; 1.1192x over previous
#include <cuda_runtime.h>
#include <cuda_bf16.h>

#define N_NODES 100000
#define N_EDGES 1600000
#define IN_FT   128
#define OUT_FT  32

#define TILE_NODES 256
#define KTILE      32          // k per phase (8 float4)
#define ROW_F4     9           // 8 float4 + 1 pad -> conflict-free LDS.128

#define CAP        64          // slots per row; Poisson(16) => P(overflow) ~ 1e-18

#define GEMM_BLOCKS ((N_NODES + TILE_NODES - 1) / TILE_NODES)   // 391
#define BIN_BLOCKS  ((N_EDGES + 255) / 256)                     // 6250

// Device-global scratch (no allocs allowed). Zero-initialized at module load;
// the gather kernel restores g_cnt/g_ovf_cnt to 0 at the end of every call,
// so the invariant "counters are 0 at kernel_launch entry" holds across the
// correctness run and all graph replays.
__device__ float  g_support[(size_t)N_NODES * OUT_FT];        // 12.8 MB
__device__ float2 g_binned[(size_t)N_NODES * CAP];            // 51.2 MB
__device__ int    g_cnt[N_NODES];
__device__ int    g_ovf_cnt;
__device__ int    g_ovf_row[N_EDGES];                         // correctness fallback
__device__ int    g_ovf_col[N_EDGES];
__device__ float  g_ovf_val[N_EDGES];

// ---------------------------------------------------------------------------
// Kernel 1 (fused): blocks [0, GEMM_BLOCKS) compute support = seq @ W
// (register-tiled, 256 nodes/block); blocks [GEMM_BLOCKS, ...) bin edges by
// destination row. The two paths touch disjoint resources (FFMA+smem vs
// L2 atomics), so the bin work hides under the GEMM.
// Slots store the PRE-MULTIPLIED support element offset (col*OUT_FT) so the
// gather's address math collapses to one IMAD.WIDE per edge.
// ---------------------------------------------------------------------------
__global__ __launch_bounds__(256, 3) void gcn_gemm_bin_kernel(
        const float* __restrict__ seq,
        const float* __restrict__ W,
        const int*   __restrict__ erow,
        const int*   __restrict__ ecol,
        const float* __restrict__ eval) {
    const int tid = threadIdx.x;

    if (blockIdx.x >= GEMM_BLOCKS) {
        // ---- bin path ----
        int e = (blockIdx.x - GEMM_BLOCKS) * 256 + tid;
        if (e >= N_EDGES) return;

        int r = __ldcs(&erow[e]);
        int c = __ldcs(&ecol[e]);
        float v = __ldcs(&eval[e]);

        int pos = atomicAdd(&g_cnt[r], 1);
        if (pos < CAP) {
            g_binned[(size_t)r * CAP + pos] =
                make_float2(__int_as_float(c * OUT_FT), v);
        } else {
            int o = atomicAdd(&g_ovf_cnt, 1);
            g_ovf_row[o] = r;
            g_ovf_col[o] = c;
            g_ovf_val[o] = v;
        }
        return;
    }

    // ---- GEMM path ----
    __shared__ float4 ssm[TILE_NODES * ROW_F4];   // 36 KB
    __shared__ float  Wsm[KTILE * OUT_FT];        // 4 KB

    const int node_base = blockIdx.x * TILE_NODES;
    const int n_slot = tid >> 2;          // 0..63
    const int j0     = (tid & 3) * 8;     // 0,8,16,24

    float acc[4][8];
    #pragma unroll
    for (int i = 0; i < 4; i++)
        #pragma unroll
        for (int j = 0; j < 8; j++) acc[i][j] = 0.f;

    const float4* seq4 = reinterpret_cast<const float4*>(seq);

    for (int kp = 0; kp < IN_FT / KTILE; kp++) {
        __syncthreads();

        reinterpret_cast<float4*>(Wsm)[tid] =
            reinterpret_cast<const float4*>(W)[kp * (KTILE * OUT_FT / 4) + tid];

        #pragma unroll
        for (int t = 0; t < 8; t++) {
            int idx = tid + t * 256;
            int row = idx >> 3;
            int k4  = idx & 7;
            int node = node_base + row;
            float4 v = make_float4(0.f, 0.f, 0.f, 0.f);
            if (node < N_NODES)
                v = seq4[(size_t)node * (IN_FT / 4) + kp * 8 + k4];
            ssm[row * ROW_F4 + k4] = v;
        }
        __syncthreads();

        #pragma unroll 2
        for (int k4 = 0; k4 < KTILE / 4; k4++) {
            float4 a0 = ssm[(n_slot      ) * ROW_F4 + k4];
            float4 a1 = ssm[(n_slot +  64) * ROW_F4 + k4];
            float4 a2 = ssm[(n_slot + 128) * ROW_F4 + k4];
            float4 a3 = ssm[(n_slot + 192) * ROW_F4 + k4];
            float a[4][4] = {{a0.x, a0.y, a0.z, a0.w},
                             {a1.x, a1.y, a1.z, a1.w},
                             {a2.x, a2.y, a2.z, a2.w},
                             {a3.x, a3.y, a3.z, a3.w}};
            #pragma unroll
            for (int kk = 0; kk < 4; kk++) {
                int k = k4 * 4 + kk;
                float4 w0 = *reinterpret_cast<const float4*>(&Wsm[k * OUT_FT + j0]);
                float4 w1 = *reinterpret_cast<const float4*>(&Wsm[k * OUT_FT + j0 + 4]);
                #pragma unroll
                for (int i = 0; i < 4; i++) {
                    acc[i][0] = fmaf(a[i][kk], w0.x, acc[i][0]);
                    acc[i][1] = fmaf(a[i][kk], w0.y, acc[i][1]);
                    acc[i][2] = fmaf(a[i][kk], w0.z, acc[i][2]);
                    acc[i][3] = fmaf(a[i][kk], w0.w, acc[i][3]);
                    acc[i][4] = fmaf(a[i][kk], w1.x, acc[i][4]);
                    acc[i][5] = fmaf(a[i][kk], w1.y, acc[i][5]);
                    acc[i][6] = fmaf(a[i][kk], w1.z, acc[i][6]);
                    acc[i][7] = fmaf(a[i][kk], w1.w, acc[i][7]);
                }
            }
        }
    }

    #pragma unroll
    for (int i = 0; i < 4; i++) {
        int node = node_base + n_slot + 64 * i;
        if (node < N_NODES) {
            float4* dst = reinterpret_cast<float4*>(&g_support[(size_t)node * OUT_FT + j0]);
            dst[0] = make_float4(acc[i][0], acc[i][1], acc[i][2], acc[i][3]);
            dst[1] = make_float4(acc[i][4], acc[i][5], acc[i][6], acc[i][7]);
        }
    }
}

// ---------------------------------------------------------------------------
// Kernel 2: gather + fused ReLU + counter cleanup. One warp per row,
// lane = output feature. Slots (pre-multiplied element offsets) are staged
// to smem with <=2 coalesced streaming loads; the 8-wide main loop batches
// 8 independent support LDGs (MLP 8) addressed off a per-lane hoisted base
// pointer (one IMAD.WIDE each). Short remainder loop (no padding -- R16
// showed padded extra iterations cost more than the serial tail).
// Each warp resets g_cnt[row]=0 after use (replaces the zero kernel).
// ---------------------------------------------------------------------------
__global__ __launch_bounds__(256) void gcn_gather_kernel(float* __restrict__ out) {
    __shared__ float2 ssl[8][CAP];    // 8 warps/block x 64 slots = 4 KB

    const int wib  = threadIdx.x >> 5;
    const int lane = threadIdx.x & 31;
    const int row  = blockIdx.x * 8 + wib;
    if (row >= N_NODES) return;

    // Independent loads issued back-to-back: slot half A, cnt, ovf counter.
    const float2* slots = &g_binned[(size_t)row * CAP];
    float2 sA = __ldcs(&slots[lane]);
    int deg = g_cnt[row];
    int nov = g_ovf_cnt;

    int n = deg < CAP ? deg : CAP;

    ssl[wib][lane] = sA;
    if (n > 32)                        // warp-uniform; ~1e-4 of rows
        ssl[wib][lane + 32] = __ldcs(&slots[lane + 32]);
    __syncwarp();

    const float* sup_lane = g_support + lane;   // hoisted per-lane base

    float acc = 0.f;
    int e = 0;
    for (; e + 8 <= n; e += 8) {
        float2 s0 = ssl[wib][e + 0];
        float2 s1 = ssl[wib][e + 1];
        float2 s2 = ssl[wib][e + 2];
        float2 s3 = ssl[wib][e + 3];
        float2 s4 = ssl[wib][e + 4];
        float2 s5 = ssl[wib][e + 5];
        float2 s6 = ssl[wib][e + 6];
        float2 s7 = ssl[wib][e + 7];
        float f0 = sup_lane[__float_as_int(s0.x)];
        float f1 = sup_lane[__float_as_int(s1.x)];
        float f2 = sup_lane[__float_as_int(s2.x)];
        float f3 = sup_lane[__float_as_int(s3.x)];
        float f4 = sup_lane[__float_as_int(s4.x)];
        float f5 = sup_lane[__float_as_int(s5.x)];
        float f6 = sup_lane[__float_as_int(s6.x)];
        float f7 = sup_lane[__float_as_int(s7.x)];
        acc = fmaf(s0.y, f0, acc);
        acc = fmaf(s1.y, f1, acc);
        acc = fmaf(s2.y, f2, acc);
        acc = fmaf(s3.y, f3, acc);
        acc = fmaf(s4.y, f4, acc);
        acc = fmaf(s5.y, f5, acc);
        acc = fmaf(s6.y, f6, acc);
        acc = fmaf(s7.y, f7, acc);
    }
    for (; e < n; e++) {
        float2 s = ssl[wib][e];
        acc = fmaf(s.y, sup_lane[__float_as_int(s.x)], acc);
    }

    // Correctness fallback: apply any overflow edges targeting this row.
    if (nov > 0) {
        for (int i = 0; i < nov; i++) {
            if (g_ovf_row[i] == row)
                acc = fmaf(g_ovf_val[i],
                           g_support[(size_t)g_ovf_col[i] * OUT_FT + lane], acc);
        }
    }

    out[(size_t)row * OUT_FT + lane] = fmaxf(acc, 0.f);

    // Cleanup for the next call/replay (deg was already consumed above).
    if (lane == 0) g_cnt[row] = 0;
    if (row == 0 && lane == 0) g_ovf_cnt = 0;
}

extern "C" void kernel_launch(void* const* d_in, const int* in_sizes, int n_in,
                              void* d_out, int out_size) {
    const float* seq  = (const float*)d_in[0];
    const float* W    = (const float*)d_in[1];
    const int*   erow = (const int*)d_in[2];
    const int*   ecol = (const int*)d_in[3];
    const float* eval = (const float*)d_in[4];
    float* out = (float*)d_out;

    // Fused GEMM (blocks [0,391)) + edge binning (blocks [391, 6641)).
    // Counters are 0 on entry (zero-init at load; reset by gather each call).
    gcn_gemm_bin_kernel<<<GEMM_BLOCKS + BIN_BLOCKS, 256>>>(seq, W, erow, ecol, eval);

    // Gather + ReLU + counter cleanup (writes every output element once).
    gcn_gather_kernel<<<(N_NODES + 7) / 8, 256>>>(out);
}